// round 2
// baseline (speedup 1.0000x reference)
#include <cuda_runtime.h>
#include <cuda_bf16.h>
#include <cstdint>

#define NN 100000
#define EE 1000000
#define HH 64
#define GG 64
#define CC 3
#define FIN1 32

// ---------------- scratch (static device allocs, allowed) ----------------
__device__ __align__(16) float g_buf1[NN * HH];   // h' (scaled hidden) ping
__device__ __align__(16) float g_buf2[NN * HH];   // scatter accumulator
__device__ float g_dinv[NN];                      // deg -> rsqrt(deg) in place
__device__ float g_cnt[GG];
__device__ __align__(16) float g_pooled[GG * HH];
__device__ float g_sum[3 * HH];
__device__ float g_sq[3 * HH];
__device__ float g_scale[3 * HH];
__device__ float g_shift[3 * HH];

// ---------------- init: deg=1 (self loop), zero the small stuff ----------------
__global__ void init_kernel() {
    int t = blockIdx.x * blockDim.x + threadIdx.x;
    if (t < NN) g_dinv[t] = 1.0f;               // self-loop contributes 1 to deg
    if (t < GG * HH) g_pooled[t] = 0.0f;
    if (t < 3 * HH) { g_sum[t] = 0.0f; g_sq[t] = 0.0f; }
    if (t < GG) g_cnt[t] = 0.0f;
}

// ---------------- degree accumulation over dst (edge_index is int32!) ----------------
__global__ void deg_kernel(const int* __restrict__ ei) {
    int e = blockIdx.x * blockDim.x + threadIdx.x;
    if (e < EE) {
        int dst = ei[EE + e];
        atomicAdd(&g_dinv[dst], 1.0f);
    }
}

// ---------------- dinv = rsqrt(deg); per-graph node counts ----------------
__global__ void dinv_cnt_kernel(const int* __restrict__ batch) {
    int n = blockIdx.x * blockDim.x + threadIdx.x;
    if (n < NN) {
        g_dinv[n] = rsqrtf(g_dinv[n]);
        atomicAdd(&g_cnt[batch[n]], 1.0f);
    }
}

// ---------------- fused (BN+ReLU) -> GEMM -> *dinv, writes h' to buf1 & buf2 ----------------
template <int FIN, int LAYER>
__global__ void gemm_kernel(const float* __restrict__ xin, const float* __restrict__ W) {
    __shared__ float xs[32][FIN];
    __shared__ float ws[FIN][64];
    const int tid = threadIdx.x;
    const int nbase = blockIdx.x * 32;

    const float* __restrict__ in = (LAYER == 0) ? xin : g_buf1;

    for (int i = tid; i < FIN * 64; i += 256) ws[i / 64][i % 64] = W[i];
    for (int i = tid; i < 32 * FIN; i += 256) {
        int r = i / FIN, c = i % FIN;
        float v = in[(size_t)(nbase + r) * FIN + c];
        if (LAYER > 0) {
            v = fmaxf(v * g_scale[(LAYER - 1) * HH + c] + g_shift[(LAYER - 1) * HH + c], 0.0f);
        }
        xs[r][c] = v;
    }
    __syncthreads();

    const int c2 = tid & 31;
    const int n0 = (tid >> 5) * 4;
    float a00 = 0.f, a01 = 0.f, a10 = 0.f, a11 = 0.f;
    float a20 = 0.f, a21 = 0.f, a30 = 0.f, a31 = 0.f;
#pragma unroll
    for (int k = 0; k < FIN; k++) {
        float w0 = ws[k][c2], w1 = ws[k][c2 + 32];
        float x0 = xs[n0 + 0][k], x1 = xs[n0 + 1][k];
        float x2 = xs[n0 + 2][k], x3 = xs[n0 + 3][k];
        a00 += x0 * w0; a01 += x0 * w1;
        a10 += x1 * w0; a11 += x1 * w1;
        a20 += x2 * w0; a21 += x2 * w1;
        a30 += x3 * w0; a31 += x3 * w1;
    }
    float acc[4][2] = {{a00, a01}, {a10, a11}, {a20, a21}, {a30, a31}};
#pragma unroll
    for (int j = 0; j < 4; j++) {
        int n = nbase + n0 + j;
        float dv = g_dinv[n];
        float v0 = acc[j][0] * dv, v1 = acc[j][1] * dv;
        size_t o = (size_t)n * 64;
        g_buf1[o + c2] = v0;      g_buf1[o + c2 + 32] = v1;
        g_buf2[o + c2] = v0;      g_buf2[o + c2 + 32] = v1;   // acc init = self-loop term
    }
}

// ---------------- edge scatter: acc[dst] += h'[src], vector RED ----------------
__global__ void scatter_kernel(const int* __restrict__ ei) {
    int t = blockIdx.x * 256 + threadIdx.x;
    int e = t >> 4;
    int q = t & 15;
    int lane = threadIdx.x & 31;
    int src = 0, dst = 0;
    if ((lane & 15) == 0) {
        src = ei[e];
        dst = ei[EE + e];
    }
    src = __shfl_sync(0xffffffffu, src, lane & 16);
    dst = __shfl_sync(0xffffffffu, dst, lane & 16);

    const float4 v = *reinterpret_cast<const float4*>(&g_buf1[(size_t)src * 64 + q * 4]);
    float* p = &g_buf2[(size_t)dst * 64 + q * 4];
    asm volatile("red.global.add.v4.f32 [%0], {%1,%2,%3,%4};"
                 :: "l"(p), "f"(v.x), "f"(v.y), "f"(v.z), "f"(v.w)
                 : "memory");
}

// ---------------- finalize: y = dinv*acc + b -> buf1; fused sum/sumsq ----------------
__global__ void finalize_kernel(const float* __restrict__ b, int layer) {
    const int tid = threadIdx.x;
    const int c = tid & 63;
    const int r = tid >> 6;            // 0..3
    const int nbase = blockIdx.x * 64;
    const float bc = b[c];
    float s = 0.f, ss = 0.f;
#pragma unroll
    for (int i = 0; i < 16; i++) {
        int n = nbase + r + i * 4;
        if (n < NN) {
            float v = g_buf2[(size_t)n * 64 + c] * g_dinv[n] + bc;
            g_buf1[(size_t)n * 64 + c] = v;
            s += v;
            ss += v * v;
        }
    }
    __shared__ float shs[4][64];
    __shared__ float shq[4][64];
    shs[r][c] = s; shq[r][c] = ss;
    __syncthreads();
    if (r == 0) {
        s  = shs[0][c] + shs[1][c] + shs[2][c] + shs[3][c];
        ss = shq[0][c] + shq[1][c] + shq[2][c] + shq[3][c];
        atomicAdd(&g_sum[layer * HH + c], s);
        atomicAdd(&g_sq[layer * HH + c], ss);
    }
}

// ---------------- BN stats -> scale/shift ----------------
__global__ void stats_kernel(const float* __restrict__ gm, const float* __restrict__ be, int layer) {
    int c = threadIdx.x;   // 64
    float invN = 1.0f / (float)NN;
    float m = g_sum[layer * HH + c] * invN;
    float v = g_sq[layer * HH + c] * invN - m * m;
    float sc = gm[c] * rsqrtf(v + 1e-5f);
    g_scale[layer * HH + c] = sc;
    g_shift[layer * HH + c] = be[c] - m * sc;
}

// ---------------- global mean pool (sum phase, BN3 applied, no relu) ----------------
__global__ void pool_kernel(const int* __restrict__ batch) {
    int t = blockIdx.x * 256 + threadIdx.x;
    int n = t >> 4;
    int q = t & 15;
    int lane = threadIdx.x & 31;
    int g = 0;
    if ((lane & 15) == 0) g = batch[n];
    g = __shfl_sync(0xffffffffu, g, lane & 16);

    int c0 = q * 4;
    float4 v = *reinterpret_cast<const float4*>(&g_buf1[(size_t)n * 64 + c0]);
    float a0 = v.x * g_scale[2 * HH + c0 + 0] + g_shift[2 * HH + c0 + 0];
    float a1 = v.y * g_scale[2 * HH + c0 + 1] + g_shift[2 * HH + c0 + 1];
    float a2 = v.z * g_scale[2 * HH + c0 + 2] + g_shift[2 * HH + c0 + 2];
    float a3 = v.w * g_scale[2 * HH + c0 + 3] + g_shift[2 * HH + c0 + 3];
    float* p = &g_pooled[(size_t)g * 64 + c0];
    asm volatile("red.global.add.v4.f32 [%0], {%1,%2,%3,%4};"
                 :: "l"(p), "f"(a0), "f"(a1), "f"(a2), "f"(a3)
                 : "memory");
}

// ---------------- head: mean, MLP (64->32 relu ->3), softmax ----------------
__global__ void head_kernel(const float* __restrict__ Wl1, const float* __restrict__ bl1,
                            const float* __restrict__ Wl2, const float* __restrict__ bl2,
                            float* __restrict__ out) {
    __shared__ float ps[GG][64];
    __shared__ float zs[GG][33];
    __shared__ float lg[GG][3];
    int tid = threadIdx.x;   // 256
    for (int i = tid; i < GG * 64; i += 256) {
        int g = i >> 6;
        ps[g][i & 63] = g_pooled[i] / fmaxf(g_cnt[g], 1.0f);
    }
    __syncthreads();
    for (int i = tid; i < GG * 32; i += 256) {
        int g = i >> 5, j = i & 31;
        float acc = bl1[j];
#pragma unroll
        for (int k = 0; k < 64; k++) acc += ps[g][k] * Wl1[k * 32 + j];
        zs[g][j] = fmaxf(acc, 0.0f);
    }
    __syncthreads();
    if (tid < GG * CC) {
        int g = tid / CC, c = tid % CC;
        float acc = bl2[c];
#pragma unroll
        for (int k = 0; k < 32; k++) acc += zs[g][k] * Wl2[k * CC + c];
        lg[g][c] = acc;
    }
    __syncthreads();
    if (tid < GG) {
        float a = lg[tid][0], b = lg[tid][1], c = lg[tid][2];
        float mx = fmaxf(a, fmaxf(b, c));
        float e0 = expf(a - mx), e1 = expf(b - mx), e2 = expf(c - mx);
        float inv = 1.0f / (e0 + e1 + e2);
        out[tid * 3 + 0] = e0 * inv;
        out[tid * 3 + 1] = e1 * inv;
        out[tid * 3 + 2] = e2 * inv;
    }
}

// ---------------- launch ----------------
extern "C" void kernel_launch(void* const* d_in, const int* in_sizes, int n_in,
                              void* d_out, int out_size) {
    const float* x     = (const float*)d_in[0];
    const int*   ei    = (const int*)d_in[1];      // int32 (JAX x64 disabled)
    const int*   batch = (const int*)d_in[2];      // int32
    const float* W1  = (const float*)d_in[3];
    const float* b1  = (const float*)d_in[4];
    const float* g1  = (const float*)d_in[5];
    const float* be1 = (const float*)d_in[6];
    const float* W2  = (const float*)d_in[7];
    const float* b2  = (const float*)d_in[8];
    const float* g2  = (const float*)d_in[9];
    const float* be2 = (const float*)d_in[10];
    const float* W3  = (const float*)d_in[11];
    const float* b3  = (const float*)d_in[12];
    const float* g3  = (const float*)d_in[13];
    const float* be3 = (const float*)d_in[14];
    const float* Wl1 = (const float*)d_in[15];
    const float* bl1 = (const float*)d_in[16];
    const float* Wl2 = (const float*)d_in[17];
    const float* bl2 = (const float*)d_in[18];
    float* out = (float*)d_out;

    const int GEMM_GRID    = NN / 32;                 // 3125
    const int SCATTER_GRID = (EE * 16) / 256;         // 62500
    const int FIN_GRID     = (NN + 63) / 64;          // 1563
    const int POOL_GRID    = (NN * 16) / 256;         // 6250

    init_kernel<<<(NN + 255) / 256, 256>>>();
    deg_kernel<<<(EE + 255) / 256, 256>>>(ei);
    dinv_cnt_kernel<<<(NN + 255) / 256, 256>>>(batch);

    // ---- layer 1 ----
    gemm_kernel<FIN1, 0><<<GEMM_GRID, 256>>>(x, W1);
    scatter_kernel<<<SCATTER_GRID, 256>>>(ei);
    finalize_kernel<<<FIN_GRID, 256>>>(b1, 0);
    stats_kernel<<<1, 64>>>(g1, be1, 0);

    // ---- layer 2 ----
    gemm_kernel<HH, 1><<<GEMM_GRID, 256>>>(nullptr, W2);
    scatter_kernel<<<SCATTER_GRID, 256>>>(ei);
    finalize_kernel<<<FIN_GRID, 256>>>(b2, 1);
    stats_kernel<<<1, 64>>>(g2, be2, 1);

    // ---- layer 3 ----
    gemm_kernel<HH, 2><<<GEMM_GRID, 256>>>(nullptr, W3);
    scatter_kernel<<<SCATTER_GRID, 256>>>(ei);
    finalize_kernel<<<FIN_GRID, 256>>>(b3, 2);
    stats_kernel<<<1, 64>>>(g3, be3, 2);

    // ---- pool + head ----
    pool_kernel<<<POOL_GRID, 256>>>(batch);
    head_kernel<<<1, 256>>>(Wl1, bl1, Wl2, bl2, out);
}

// round 3
// speedup vs baseline: 1.2629x; 1.2629x over previous
#include <cuda_runtime.h>
#include <cuda_bf16.h>
#include <cstdint>

#define NN 100000
#define EE 1000000
#define HH 64
#define GG 64
#define CC 3
#define FIN1 32
#define SCAN_BLOCKS 98            // 98*1024 = 100352 >= NN+1

// ---------------- scratch ----------------
__device__ __align__(16) float g_buf1[NN * HH];   // h' = (in@W)*dinv   (gather input)
__device__ __align__(16) float g_buf2[NN * HH];   // y  = propagated+b  (gemm input next layer)
__device__ float g_dinv[NN];
__device__ float g_cnt[GG];
__device__ __align__(16) float g_pooled[GG * HH];
__device__ float g_sum[3 * HH];
__device__ float g_sq[3 * HH];
__device__ float g_scale[3 * HH];
__device__ float g_shift[3 * HH];
// CSR
__device__ int g_deg[NN];
__device__ int g_rowptr[NN + 1];
__device__ int g_next[NN];
__device__ int g_col[EE];
__device__ int g_bsum[SCAN_BLOCKS];

// ---------------- init ----------------
__global__ void init_kernel() {
    int t = blockIdx.x * blockDim.x + threadIdx.x;
    if (t < NN) g_deg[t] = 0;
    if (t < GG * HH) g_pooled[t] = 0.0f;
    if (t < 3 * HH) { g_sum[t] = 0.0f; g_sq[t] = 0.0f; }
    if (t < GG) g_cnt[t] = 0.0f;
}

// ---------------- in-degree histogram ----------------
__global__ void hist_kernel(const int* __restrict__ ei) {
    int e = blockIdx.x * blockDim.x + threadIdx.x;
    if (e < EE) atomicAdd(&g_deg[ei[EE + e]], 1);
}

// ---------------- dinv = rsqrt(deg+1 self loop); per-graph counts ----------------
__global__ void dinv_cnt_kernel(const int* __restrict__ batch) {
    int n = blockIdx.x * blockDim.x + threadIdx.x;
    if (n < NN) {
        g_dinv[n] = rsqrtf(1.0f + (float)g_deg[n]);
        atomicAdd(&g_cnt[batch[n]], 1.0f);
    }
}

// ---------------- exclusive scan of g_deg -> g_rowptr ----------------
__global__ void scan1_kernel() {
    __shared__ int sh[1024];
    int tid = threadIdx.x;
    int gid = blockIdx.x * 1024 + tid;
    int v = (gid < NN) ? g_deg[gid] : 0;
    sh[tid] = v;
    __syncthreads();
    for (int off = 1; off < 1024; off <<= 1) {
        int t = (tid >= off) ? sh[tid - off] : 0;
        __syncthreads();
        sh[tid] += t;
        __syncthreads();
    }
    if (gid <= NN) g_rowptr[gid] = sh[tid] - v;   // exclusive
    if (tid == 1023) g_bsum[blockIdx.x] = sh[1023];
}

__global__ void scan2_kernel() {
    int acc = 0;
    for (int i = 0; i < SCAN_BLOCKS; i++) { int t = g_bsum[i]; g_bsum[i] = acc; acc += t; }
}

__global__ void scan3_kernel() {
    int gid = blockIdx.x * 1024 + threadIdx.x;
    if (gid <= NN) {
        int v = g_rowptr[gid] + g_bsum[blockIdx.x];
        g_rowptr[gid] = v;
        if (gid < NN) g_next[gid] = v;
    }
}

// ---------------- CSR fill: col list grouped by dst ----------------
__global__ void fill_kernel(const int* __restrict__ ei) {
    int e = blockIdx.x * blockDim.x + threadIdx.x;
    if (e < EE) {
        int dst = ei[EE + e];
        int pos = atomicAdd(&g_next[dst], 1);
        g_col[pos] = ei[e];
    }
}

// ---------------- GEMM: (BN+ReLU of buf2 | x) @ W, * dinv -> buf1 ----------------
// 64-node tile, thread = 4 nodes x 4 channels, float4 smem traffic.
template <int FIN, int LAYER>
__global__ void __launch_bounds__(256) gemm_kernel(const float* __restrict__ xin,
                                                   const float* __restrict__ W) {
    __shared__ float xs[64][FIN];
    __shared__ float ws[FIN][64];
    const int tid = threadIdx.x;
    const int nbase = blockIdx.x * 64;
    const float* __restrict__ in = (LAYER == 0) ? xin : g_buf2;

    for (int i = tid; i < FIN * 64; i += 256) ws[i >> 6][i & 63] = W[i];

    constexpr int F4 = FIN / 4;
    for (int i = tid; i < 64 * F4; i += 256) {
        int r = i / F4, c4 = i % F4;
        int n = nbase + r;
        float4 v = {0.f, 0.f, 0.f, 0.f};
        if (n < NN) v = *reinterpret_cast<const float4*>(&in[(size_t)n * FIN + c4 * 4]);
        if (LAYER > 0) {
            int c = c4 * 4;
            v.x = fmaxf(fmaf(v.x, g_scale[(LAYER - 1) * HH + c + 0], g_shift[(LAYER - 1) * HH + c + 0]), 0.f);
            v.y = fmaxf(fmaf(v.y, g_scale[(LAYER - 1) * HH + c + 1], g_shift[(LAYER - 1) * HH + c + 1]), 0.f);
            v.z = fmaxf(fmaf(v.z, g_scale[(LAYER - 1) * HH + c + 2], g_shift[(LAYER - 1) * HH + c + 2]), 0.f);
            v.w = fmaxf(fmaf(v.w, g_scale[(LAYER - 1) * HH + c + 3], g_shift[(LAYER - 1) * HH + c + 3]), 0.f);
        }
        *reinterpret_cast<float4*>(&xs[r][c4 * 4]) = v;
    }
    __syncthreads();

    const int cg = tid & 15;          // column group: cols cg*4 .. cg*4+3
    const int n0 = (tid >> 4) * 4;    // nodes n0 .. n0+3
    float4 acc[4] = {{0,0,0,0},{0,0,0,0},{0,0,0,0},{0,0,0,0}};
#pragma unroll
    for (int k4 = 0; k4 < F4; k4++) {
        float4 xv[4];
#pragma unroll
        for (int j = 0; j < 4; j++)
            xv[j] = *reinterpret_cast<const float4*>(&xs[n0 + j][k4 * 4]);
#pragma unroll
        for (int kk = 0; kk < 4; kk++) {
            float4 wv = *reinterpret_cast<const float4*>(&ws[k4 * 4 + kk][cg * 4]);
#pragma unroll
            for (int j = 0; j < 4; j++) {
                float e = (&xv[j].x)[kk];
                acc[j].x = fmaf(e, wv.x, acc[j].x);
                acc[j].y = fmaf(e, wv.y, acc[j].y);
                acc[j].z = fmaf(e, wv.z, acc[j].z);
                acc[j].w = fmaf(e, wv.w, acc[j].w);
            }
        }
    }
#pragma unroll
    for (int j = 0; j < 4; j++) {
        int n = nbase + n0 + j;
        if (n < NN) {
            float dv = g_dinv[n];
            float4 a = acc[j];
            a.x *= dv; a.y *= dv; a.z *= dv; a.w *= dv;
            *reinterpret_cast<float4*>(&g_buf1[(size_t)n * 64 + cg * 4]) = a;
        }
    }
}

// ---------------- CSR gather: y[n] = dinv[n]*(h'[n] + sum h'[src]) + b; BN sums ----------------
__global__ void __launch_bounds__(256) gather_kernel(const float* __restrict__ b, int layer) {
    const int tid = threadIdx.x;
    const int q = tid & 15;
    const int n = blockIdx.x * 16 + (tid >> 4);   // NN/16 = 6250 exact
    const int c0 = q * 4;

    float4 acc = *reinterpret_cast<const float4*>(&g_buf1[(size_t)n * 64 + c0]);  // self
    const int beg = g_rowptr[n];
    const int end = g_rowptr[n + 1];
    for (int i = beg; i < end; i++) {
        int src = g_col[i];
        float4 v = *reinterpret_cast<const float4*>(&g_buf1[(size_t)src * 64 + c0]);
        acc.x += v.x; acc.y += v.y; acc.z += v.z; acc.w += v.w;
    }
    const float dv = g_dinv[n];
    acc.x = fmaf(acc.x, dv, b[c0 + 0]);
    acc.y = fmaf(acc.y, dv, b[c0 + 1]);
    acc.z = fmaf(acc.z, dv, b[c0 + 2]);
    acc.w = fmaf(acc.w, dv, b[c0 + 3]);
    *reinterpret_cast<float4*>(&g_buf2[(size_t)n * 64 + c0]) = acc;

    // BN partial sums: reduce the two 16-thread groups of each warp, then smem, then global
    float4 sq = {acc.x * acc.x, acc.y * acc.y, acc.z * acc.z, acc.w * acc.w};
    acc.x += __shfl_xor_sync(0xffffffffu, acc.x, 16);
    acc.y += __shfl_xor_sync(0xffffffffu, acc.y, 16);
    acc.z += __shfl_xor_sync(0xffffffffu, acc.z, 16);
    acc.w += __shfl_xor_sync(0xffffffffu, acc.w, 16);
    sq.x += __shfl_xor_sync(0xffffffffu, sq.x, 16);
    sq.y += __shfl_xor_sync(0xffffffffu, sq.y, 16);
    sq.z += __shfl_xor_sync(0xffffffffu, sq.z, 16);
    sq.w += __shfl_xor_sync(0xffffffffu, sq.w, 16);

    __shared__ float ss[8][64];
    __shared__ float sg[8][64];
    int w = tid >> 5, lane = tid & 31;
    if (lane < 16) {
        ss[w][c0 + 0] = acc.x; ss[w][c0 + 1] = acc.y; ss[w][c0 + 2] = acc.z; ss[w][c0 + 3] = acc.w;
        sg[w][c0 + 0] = sq.x;  sg[w][c0 + 1] = sq.y;  sg[w][c0 + 2] = sq.z;  sg[w][c0 + 3] = sq.w;
    }
    __syncthreads();
    if (tid < 64) {
        float s = 0.f, s2 = 0.f;
#pragma unroll
        for (int ww = 0; ww < 8; ww++) { s += ss[ww][tid]; s2 += sg[ww][tid]; }
        atomicAdd(&g_sum[layer * HH + tid], s);
        atomicAdd(&g_sq[layer * HH + tid], s2);
    }
}

// ---------------- BN stats -> scale/shift ----------------
__global__ void stats_kernel(const float* __restrict__ gm, const float* __restrict__ be, int layer) {
    int c = threadIdx.x;   // 64
    float invN = 1.0f / (float)NN;
    float m = g_sum[layer * HH + c] * invN;
    float v = g_sq[layer * HH + c] * invN - m * m;
    float sc = gm[c] * rsqrtf(v + 1e-5f);
    g_scale[layer * HH + c] = sc;
    g_shift[layer * HH + c] = be[c] - m * sc;
}

// ---------------- global mean pool (BN3 applied, no relu) ----------------
__global__ void pool_kernel(const int* __restrict__ batch) {
    int t = blockIdx.x * 256 + threadIdx.x;
    int n = t >> 4;
    int q = t & 15;
    int lane = threadIdx.x & 31;
    int g = 0;
    if ((lane & 15) == 0) g = batch[n];
    g = __shfl_sync(0xffffffffu, g, lane & 16);

    int c0 = q * 4;
    float4 v = *reinterpret_cast<const float4*>(&g_buf2[(size_t)n * 64 + c0]);
    float a0 = fmaf(v.x, g_scale[2 * HH + c0 + 0], g_shift[2 * HH + c0 + 0]);
    float a1 = fmaf(v.y, g_scale[2 * HH + c0 + 1], g_shift[2 * HH + c0 + 1]);
    float a2 = fmaf(v.z, g_scale[2 * HH + c0 + 2], g_shift[2 * HH + c0 + 2]);
    float a3 = fmaf(v.w, g_scale[2 * HH + c0 + 3], g_shift[2 * HH + c0 + 3]);
    float* p = &g_pooled[(size_t)g * 64 + c0];
    asm volatile("red.global.add.v4.f32 [%0], {%1,%2,%3,%4};"
                 :: "l"(p), "f"(a0), "f"(a1), "f"(a2), "f"(a3)
                 : "memory");
}

// ---------------- head ----------------
__global__ void head_kernel(const float* __restrict__ Wl1, const float* __restrict__ bl1,
                            const float* __restrict__ Wl2, const float* __restrict__ bl2,
                            float* __restrict__ out) {
    __shared__ float ps[GG][64];
    __shared__ float zs[GG][33];
    __shared__ float lg[GG][3];
    int tid = threadIdx.x;   // 256
    for (int i = tid; i < GG * 64; i += 256) {
        int g = i >> 6;
        ps[g][i & 63] = g_pooled[i] / fmaxf(g_cnt[g], 1.0f);
    }
    __syncthreads();
    for (int i = tid; i < GG * 32; i += 256) {
        int g = i >> 5, j = i & 31;
        float acc = bl1[j];
#pragma unroll
        for (int k = 0; k < 64; k++) acc += ps[g][k] * Wl1[k * 32 + j];
        zs[g][j] = fmaxf(acc, 0.0f);
    }
    __syncthreads();
    if (tid < GG * CC) {
        int g = tid / CC, c = tid % CC;
        float acc = bl2[c];
#pragma unroll
        for (int k = 0; k < 32; k++) acc += zs[g][k] * Wl2[k * CC + c];
        lg[g][c] = acc;
    }
    __syncthreads();
    if (tid < GG) {
        float a = lg[tid][0], b = lg[tid][1], c = lg[tid][2];
        float mx = fmaxf(a, fmaxf(b, c));
        float e0 = expf(a - mx), e1 = expf(b - mx), e2 = expf(c - mx);
        float inv = 1.0f / (e0 + e1 + e2);
        out[tid * 3 + 0] = e0 * inv;
        out[tid * 3 + 1] = e1 * inv;
        out[tid * 3 + 2] = e2 * inv;
    }
}

// ---------------- launch ----------------
extern "C" void kernel_launch(void* const* d_in, const int* in_sizes, int n_in,
                              void* d_out, int out_size) {
    const float* x     = (const float*)d_in[0];
    const int*   ei    = (const int*)d_in[1];
    const int*   batch = (const int*)d_in[2];
    const float* W1  = (const float*)d_in[3];
    const float* b1  = (const float*)d_in[4];
    const float* g1  = (const float*)d_in[5];
    const float* be1 = (const float*)d_in[6];
    const float* W2  = (const float*)d_in[7];
    const float* b2  = (const float*)d_in[8];
    const float* g2  = (const float*)d_in[9];
    const float* be2 = (const float*)d_in[10];
    const float* W3  = (const float*)d_in[11];
    const float* b3  = (const float*)d_in[12];
    const float* g3  = (const float*)d_in[13];
    const float* be3 = (const float*)d_in[14];
    const float* Wl1 = (const float*)d_in[15];
    const float* bl1 = (const float*)d_in[16];
    const float* Wl2 = (const float*)d_in[17];
    const float* bl2 = (const float*)d_in[18];
    float* out = (float*)d_out;

    const int GEMM_GRID   = (NN + 63) / 64;           // 1563
    const int GATHER_GRID = NN / 16;                  // 6250
    const int POOL_GRID   = (NN * 16) / 256;          // 6250

    init_kernel<<<(NN + 255) / 256, 256>>>();
    hist_kernel<<<(EE + 255) / 256, 256>>>(ei);
    dinv_cnt_kernel<<<(NN + 255) / 256, 256>>>(batch);
    scan1_kernel<<<SCAN_BLOCKS, 1024>>>();
    scan2_kernel<<<1, 1>>>();
    scan3_kernel<<<SCAN_BLOCKS, 1024>>>();
    fill_kernel<<<(EE + 255) / 256, 256>>>(ei);

    // ---- layer 1 ----
    gemm_kernel<FIN1, 0><<<GEMM_GRID, 256>>>(x, W1);
    gather_kernel<<<GATHER_GRID, 256>>>(b1, 0);
    stats_kernel<<<1, 64>>>(g1, be1, 0);

    // ---- layer 2 ----
    gemm_kernel<HH, 1><<<GEMM_GRID, 256>>>(nullptr, W2);
    gather_kernel<<<GATHER_GRID, 256>>>(b2, 1);
    stats_kernel<<<1, 64>>>(g2, be2, 1);

    // ---- layer 3 ----
    gemm_kernel<HH, 2><<<GEMM_GRID, 256>>>(nullptr, W3);
    gather_kernel<<<GATHER_GRID, 256>>>(b3, 2);
    stats_kernel<<<1, 64>>>(g3, be3, 2);

    // ---- pool + head ----
    pool_kernel<<<POOL_GRID, 256>>>(batch);
    head_kernel<<<1, 256>>>(Wl1, bl1, Wl2, bl2, out);
}

// round 4
// speedup vs baseline: 1.4400x; 1.1402x over previous
#include <cuda_runtime.h>
#include <cuda_fp16.h>
#include <cuda_bf16.h>
#include <cstdint>

#define NN 100000
#define EE 1000000
#define HH 64
#define GG 64
#define CC 3
#define FIN1 32
#define SCAN_BLOCKS 98            // 98*1024 = 100352 >= NN+1

// ---------------- scratch ----------------
__device__ __align__(16) __half g_hp[NN * HH];    // h' = (in@W)*dinv, fp16 rows (128B)
__device__ __align__(16) float g_buf2[NN * HH];   // y  = propagated+b (fp32)
__device__ float g_dinv[NN];
__device__ float g_cnt[GG];
__device__ __align__(16) float g_pooled[GG * HH];
__device__ float g_sum[3 * HH];
__device__ float g_sq[3 * HH];
__device__ float g_scale[3 * HH];
__device__ float g_shift[3 * HH];
// CSR
__device__ int g_deg[NN];
__device__ int g_rowptr[NN + 1];
__device__ int g_next[NN];
__device__ int g_col[EE];
__device__ int g_bsum[SCAN_BLOCKS];

// ---------------- init ----------------
__global__ void init_kernel() {
    int t = blockIdx.x * blockDim.x + threadIdx.x;
    if (t < NN) g_deg[t] = 0;
    if (t < GG * HH) g_pooled[t] = 0.0f;
    if (t < 3 * HH) { g_sum[t] = 0.0f; g_sq[t] = 0.0f; }
    if (t < GG) g_cnt[t] = 0.0f;
}

// ---------------- in-degree histogram ----------------
__global__ void hist_kernel(const int* __restrict__ ei) {
    int e = blockIdx.x * blockDim.x + threadIdx.x;
    if (e < EE) atomicAdd(&g_deg[ei[EE + e]], 1);
}

// ---------------- dinv = rsqrt(deg+1); per-graph counts ----------------
__global__ void dinv_cnt_kernel(const int* __restrict__ batch) {
    int n = blockIdx.x * blockDim.x + threadIdx.x;
    if (n < NN) {
        g_dinv[n] = rsqrtf(1.0f + (float)g_deg[n]);
        atomicAdd(&g_cnt[batch[n]], 1.0f);
    }
}

// ---------------- exclusive scan of g_deg -> g_rowptr ----------------
__global__ void scan1_kernel() {
    __shared__ int sh[1024];
    int tid = threadIdx.x;
    int gid = blockIdx.x * 1024 + tid;
    int v = (gid < NN) ? g_deg[gid] : 0;
    sh[tid] = v;
    __syncthreads();
    for (int off = 1; off < 1024; off <<= 1) {
        int t = (tid >= off) ? sh[tid - off] : 0;
        __syncthreads();
        sh[tid] += t;
        __syncthreads();
    }
    if (gid <= NN) g_rowptr[gid] = sh[tid] - v;   // exclusive
    if (tid == 1023) g_bsum[blockIdx.x] = sh[1023];
}

__global__ void scan2_kernel() {
    int acc = 0;
    for (int i = 0; i < SCAN_BLOCKS; i++) { int t = g_bsum[i]; g_bsum[i] = acc; acc += t; }
}

__global__ void scan3_kernel() {
    int gid = blockIdx.x * 1024 + threadIdx.x;
    if (gid <= NN) {
        int v = g_rowptr[gid] + g_bsum[blockIdx.x];
        g_rowptr[gid] = v;
        if (gid < NN) g_next[gid] = v;
    }
}

// ---------------- CSR fill ----------------
__global__ void fill_kernel(const int* __restrict__ ei) {
    int e = blockIdx.x * blockDim.x + threadIdx.x;
    if (e < EE) {
        int dst = ei[EE + e];
        int pos = atomicAdd(&g_next[dst], 1);
        g_col[pos] = ei[e];
    }
}

// ---------------- GEMM: (BN+ReLU of buf2 | x) @ W, * dinv -> g_hp (fp16) ----------------
template <int FIN, int LAYER>
__global__ void __launch_bounds__(256) gemm_kernel(const float* __restrict__ xin,
                                                   const float* __restrict__ W) {
    __shared__ float xs[64][FIN];
    __shared__ float ws[FIN][64];
    const int tid = threadIdx.x;
    const int nbase = blockIdx.x * 64;
    const float* __restrict__ in = (LAYER == 0) ? xin : g_buf2;

    for (int i = tid; i < FIN * 64; i += 256) ws[i >> 6][i & 63] = W[i];

    constexpr int F4 = FIN / 4;
    for (int i = tid; i < 64 * F4; i += 256) {
        int r = i / F4, c4 = i % F4;
        int n = nbase + r;
        float4 v = {0.f, 0.f, 0.f, 0.f};
        if (n < NN) v = *reinterpret_cast<const float4*>(&in[(size_t)n * FIN + c4 * 4]);
        if (LAYER > 0) {
            int c = c4 * 4;
            v.x = fmaxf(fmaf(v.x, g_scale[(LAYER - 1) * HH + c + 0], g_shift[(LAYER - 1) * HH + c + 0]), 0.f);
            v.y = fmaxf(fmaf(v.y, g_scale[(LAYER - 1) * HH + c + 1], g_shift[(LAYER - 1) * HH + c + 1]), 0.f);
            v.z = fmaxf(fmaf(v.z, g_scale[(LAYER - 1) * HH + c + 2], g_shift[(LAYER - 1) * HH + c + 2]), 0.f);
            v.w = fmaxf(fmaf(v.w, g_scale[(LAYER - 1) * HH + c + 3], g_shift[(LAYER - 1) * HH + c + 3]), 0.f);
        }
        *reinterpret_cast<float4*>(&xs[r][c4 * 4]) = v;
    }
    __syncthreads();

    const int cg = tid & 15;          // column group: cols cg*4 .. cg*4+3
    const int n0 = (tid >> 4) * 4;    // nodes n0 .. n0+3
    float4 acc[4] = {{0,0,0,0},{0,0,0,0},{0,0,0,0},{0,0,0,0}};
#pragma unroll
    for (int k4 = 0; k4 < F4; k4++) {
        float4 xv[4];
#pragma unroll
        for (int j = 0; j < 4; j++)
            xv[j] = *reinterpret_cast<const float4*>(&xs[n0 + j][k4 * 4]);
#pragma unroll
        for (int kk = 0; kk < 4; kk++) {
            float4 wv = *reinterpret_cast<const float4*>(&ws[k4 * 4 + kk][cg * 4]);
#pragma unroll
            for (int j = 0; j < 4; j++) {
                float e = (&xv[j].x)[kk];
                acc[j].x = fmaf(e, wv.x, acc[j].x);
                acc[j].y = fmaf(e, wv.y, acc[j].y);
                acc[j].z = fmaf(e, wv.z, acc[j].z);
                acc[j].w = fmaf(e, wv.w, acc[j].w);
            }
        }
    }
#pragma unroll
    for (int j = 0; j < 4; j++) {
        int n = nbase + n0 + j;
        if (n < NN) {
            float dv = g_dinv[n];
            float4 a = acc[j];
            union { uint2 u; __half2 h[2]; } pk;
            pk.h[0] = __floats2half2_rn(a.x * dv, a.y * dv);
            pk.h[1] = __floats2half2_rn(a.z * dv, a.w * dv);
            *reinterpret_cast<uint2*>(&g_hp[(size_t)n * 64 + cg * 4]) = pk.u;
        }
    }
}

// ---------------- fp16 row accumulate helper ----------------
__device__ __forceinline__ void add8(float* acc, float4 v) {
    const __half2* h = reinterpret_cast<const __half2*>(&v);
#pragma unroll
    for (int k = 0; k < 4; k++) {
        float2 f = __half22float2(h[k]);
        acc[2 * k]     += f.x;
        acc[2 * k + 1] += f.y;
    }
}

// ---------------- CSR gather: y[n] = dinv[n]*(h'[n] + sum h'[src]) + b; BN sums ----------------
// 8 threads per node, each covers 8 channels (one 16B fp16 load per row).
__global__ void __launch_bounds__(256) gather_kernel(const float* __restrict__ b, int layer) {
    const int tid = threadIdx.x;
    const int q = tid & 7;
    const int n = blockIdx.x * 32 + (tid >> 3);   // NN/32 = 3125 exact
    const int c0 = q * 8;

    float acc[8];
    {   // self term
        float4 v = *reinterpret_cast<const float4*>(&g_hp[(size_t)n * 64 + c0]);
        const __half2* h = reinterpret_cast<const __half2*>(&v);
#pragma unroll
        for (int k = 0; k < 4; k++) {
            float2 f = __half22float2(h[k]);
            acc[2 * k] = f.x; acc[2 * k + 1] = f.y;
        }
    }

    const int beg = g_rowptr[n];
    const int end = g_rowptr[n + 1];
    int i = beg;
    for (; i + 4 <= end; i += 4) {
        int s0 = g_col[i], s1 = g_col[i + 1], s2 = g_col[i + 2], s3 = g_col[i + 3];
        float4 v0 = *reinterpret_cast<const float4*>(&g_hp[(size_t)s0 * 64 + c0]);
        float4 v1 = *reinterpret_cast<const float4*>(&g_hp[(size_t)s1 * 64 + c0]);
        float4 v2 = *reinterpret_cast<const float4*>(&g_hp[(size_t)s2 * 64 + c0]);
        float4 v3 = *reinterpret_cast<const float4*>(&g_hp[(size_t)s3 * 64 + c0]);
        add8(acc, v0); add8(acc, v1); add8(acc, v2); add8(acc, v3);
    }
    for (; i < end; i++) {
        int s = g_col[i];
        float4 v = *reinterpret_cast<const float4*>(&g_hp[(size_t)s * 64 + c0]);
        add8(acc, v);
    }

    const float dv = g_dinv[n];
    float4 bv0 = *reinterpret_cast<const float4*>(&b[c0]);
    float4 bv1 = *reinterpret_cast<const float4*>(&b[c0 + 4]);
    float y[8];
    y[0] = fmaf(acc[0], dv, bv0.x); y[1] = fmaf(acc[1], dv, bv0.y);
    y[2] = fmaf(acc[2], dv, bv0.z); y[3] = fmaf(acc[3], dv, bv0.w);
    y[4] = fmaf(acc[4], dv, bv1.x); y[5] = fmaf(acc[5], dv, bv1.y);
    y[6] = fmaf(acc[6], dv, bv1.z); y[7] = fmaf(acc[7], dv, bv1.w);
    *reinterpret_cast<float4*>(&g_buf2[(size_t)n * 64 + c0])     = make_float4(y[0], y[1], y[2], y[3]);
    *reinterpret_cast<float4*>(&g_buf2[(size_t)n * 64 + c0 + 4]) = make_float4(y[4], y[5], y[6], y[7]);

    // BN partial sums: 4 nodes/warp share channel-slot pattern (lanes l, l^8, l^16, l^24)
    float s[8], s2[8];
#pragma unroll
    for (int k = 0; k < 8; k++) { s[k] = y[k]; s2[k] = y[k] * y[k]; }
#pragma unroll
    for (int k = 0; k < 8; k++) {
        s[k]  += __shfl_xor_sync(0xffffffffu, s[k], 8);
        s2[k] += __shfl_xor_sync(0xffffffffu, s2[k], 8);
        s[k]  += __shfl_xor_sync(0xffffffffu, s[k], 16);
        s2[k] += __shfl_xor_sync(0xffffffffu, s2[k], 16);
    }
    __shared__ float ss[8][64];
    __shared__ float sg[8][64];
    int w = tid >> 5, lane = tid & 31;
    if (lane < 8) {
        *reinterpret_cast<float4*>(&ss[w][c0])     = make_float4(s[0], s[1], s[2], s[3]);
        *reinterpret_cast<float4*>(&ss[w][c0 + 4]) = make_float4(s[4], s[5], s[6], s[7]);
        *reinterpret_cast<float4*>(&sg[w][c0])     = make_float4(s2[0], s2[1], s2[2], s2[3]);
        *reinterpret_cast<float4*>(&sg[w][c0 + 4]) = make_float4(s2[4], s2[5], s2[6], s2[7]);
    }
    __syncthreads();
    if (tid < 64) {
        float a = 0.f, a2 = 0.f;
#pragma unroll
        for (int ww = 0; ww < 8; ww++) { a += ss[ww][tid]; a2 += sg[ww][tid]; }
        atomicAdd(&g_sum[layer * HH + tid], a);
        atomicAdd(&g_sq[layer * HH + tid], a2);
    }
}

// ---------------- BN stats -> scale/shift ----------------
__global__ void stats_kernel(const float* __restrict__ gm, const float* __restrict__ be, int layer) {
    int c = threadIdx.x;   // 64
    float invN = 1.0f / (float)NN;
    float m = g_sum[layer * HH + c] * invN;
    float v = g_sq[layer * HH + c] * invN - m * m;
    float sc = gm[c] * rsqrtf(v + 1e-5f);
    g_scale[layer * HH + c] = sc;
    g_shift[layer * HH + c] = be[c] - m * sc;
}

// ---------------- global mean pool (BN3 applied) ----------------
__global__ void pool_kernel(const int* __restrict__ batch) {
    int t = blockIdx.x * 256 + threadIdx.x;
    int n = t >> 4;
    int q = t & 15;
    int lane = threadIdx.x & 31;
    int g = 0;
    if ((lane & 15) == 0) g = batch[n];
    g = __shfl_sync(0xffffffffu, g, lane & 16);

    int c0 = q * 4;
    float4 v = *reinterpret_cast<const float4*>(&g_buf2[(size_t)n * 64 + c0]);
    float a0 = fmaf(v.x, g_scale[2 * HH + c0 + 0], g_shift[2 * HH + c0 + 0]);
    float a1 = fmaf(v.y, g_scale[2 * HH + c0 + 1], g_shift[2 * HH + c0 + 1]);
    float a2 = fmaf(v.z, g_scale[2 * HH + c0 + 2], g_shift[2 * HH + c0 + 2]);
    float a3 = fmaf(v.w, g_scale[2 * HH + c0 + 3], g_shift[2 * HH + c0 + 3]);
    float* p = &g_pooled[(size_t)g * 64 + c0];
    asm volatile("red.global.add.v4.f32 [%0], {%1,%2,%3,%4};"
                 :: "l"(p), "f"(a0), "f"(a1), "f"(a2), "f"(a3)
                 : "memory");
}

// ---------------- head ----------------
__global__ void head_kernel(const float* __restrict__ Wl1, const float* __restrict__ bl1,
                            const float* __restrict__ Wl2, const float* __restrict__ bl2,
                            float* __restrict__ out) {
    __shared__ float ps[GG][64];
    __shared__ float zs[GG][33];
    __shared__ float lg[GG][3];
    int tid = threadIdx.x;   // 256
    for (int i = tid; i < GG * 64; i += 256) {
        int g = i >> 6;
        ps[g][i & 63] = g_pooled[i] / fmaxf(g_cnt[g], 1.0f);
    }
    __syncthreads();
    for (int i = tid; i < GG * 32; i += 256) {
        int g = i >> 5, j = i & 31;
        float acc = bl1[j];
#pragma unroll
        for (int k = 0; k < 64; k++) acc += ps[g][k] * Wl1[k * 32 + j];
        zs[g][j] = fmaxf(acc, 0.0f);
    }
    __syncthreads();
    if (tid < GG * CC) {
        int g = tid / CC, c = tid % CC;
        float acc = bl2[c];
#pragma unroll
        for (int k = 0; k < 32; k++) acc += zs[g][k] * Wl2[k * CC + c];
        lg[g][c] = acc;
    }
    __syncthreads();
    if (tid < GG) {
        float a = lg[tid][0], b = lg[tid][1], c = lg[tid][2];
        float mx = fmaxf(a, fmaxf(b, c));
        float e0 = expf(a - mx), e1 = expf(b - mx), e2 = expf(c - mx);
        float inv = 1.0f / (e0 + e1 + e2);
        out[tid * 3 + 0] = e0 * inv;
        out[tid * 3 + 1] = e1 * inv;
        out[tid * 3 + 2] = e2 * inv;
    }
}

// ---------------- launch ----------------
extern "C" void kernel_launch(void* const* d_in, const int* in_sizes, int n_in,
                              void* d_out, int out_size) {
    const float* x     = (const float*)d_in[0];
    const int*   ei    = (const int*)d_in[1];
    const int*   batch = (const int*)d_in[2];
    const float* W1  = (const float*)d_in[3];
    const float* b1  = (const float*)d_in[4];
    const float* g1  = (const float*)d_in[5];
    const float* be1 = (const float*)d_in[6];
    const float* W2  = (const float*)d_in[7];
    const float* b2  = (const float*)d_in[8];
    const float* g2  = (const float*)d_in[9];
    const float* be2 = (const float*)d_in[10];
    const float* W3  = (const float*)d_in[11];
    const float* b3  = (const float*)d_in[12];
    const float* g3  = (const float*)d_in[13];
    const float* be3 = (const float*)d_in[14];
    const float* Wl1 = (const float*)d_in[15];
    const float* bl1 = (const float*)d_in[16];
    const float* Wl2 = (const float*)d_in[17];
    const float* bl2 = (const float*)d_in[18];
    float* out = (float*)d_out;

    const int GEMM_GRID   = (NN + 63) / 64;           // 1563
    const int GATHER_GRID = NN / 32;                  // 3125
    const int POOL_GRID   = (NN * 16) / 256;          // 6250

    init_kernel<<<(NN + 255) / 256, 256>>>();
    hist_kernel<<<(EE + 255) / 256, 256>>>(ei);
    dinv_cnt_kernel<<<(NN + 255) / 256, 256>>>(batch);
    scan1_kernel<<<SCAN_BLOCKS, 1024>>>();
    scan2_kernel<<<1, 1>>>();
    scan3_kernel<<<SCAN_BLOCKS, 1024>>>();
    fill_kernel<<<(EE + 255) / 256, 256>>>(ei);

    // ---- layer 1 ----
    gemm_kernel<FIN1, 0><<<GEMM_GRID, 256>>>(x, W1);
    gather_kernel<<<GATHER_GRID, 256>>>(b1, 0);
    stats_kernel<<<1, 64>>>(g1, be1, 0);

    // ---- layer 2 ----
    gemm_kernel<HH, 1><<<GEMM_GRID, 256>>>(nullptr, W2);
    gather_kernel<<<GATHER_GRID, 256>>>(b2, 1);
    stats_kernel<<<1, 64>>>(g2, be2, 1);

    // ---- layer 3 ----
    gemm_kernel<HH, 2><<<GEMM_GRID, 256>>>(nullptr, W3);
    gather_kernel<<<GATHER_GRID, 256>>>(b3, 2);
    stats_kernel<<<1, 64>>>(g3, be3, 2);

    // ---- pool + head ----
    pool_kernel<<<POOL_GRID, 256>>>(batch);
    head_kernel<<<1, 256>>>(Wl1, bl1, Wl2, bl2, out);
}